// round 10
// baseline (speedup 1.0000x reference)
#include <cuda_runtime.h>

// ---------------------------------------------------------------------------
// Problem constants (fixed shapes from setup_inputs)
// ---------------------------------------------------------------------------
#define NB   4
#define CIN  256          // CH == CL == 256
#define CCC  64           // compressed channels
#define HH   128
#define WW   128
#define HWX  (HH*WW)      // 16384
#define H2   64
#define W2   64
#define HW2  (H2*W2)      // 4096

// ---------------------------------------------------------------------------
// Device-global scratch (no cudaMalloc allowed)
// ---------------------------------------------------------------------------
__device__ float g_chf  [NB*CCC*HWX];   // 16 MB
__device__ float g_chf2 [NB*CCC*HWX];   // 16 MB
__device__ float g_clf  [NB*CCC*HW2];   // 4 MB
__device__ float g_mhh  [NB*9 *HWX];    // mask_hr_hr -> mask_hr (in-place add)
__device__ float g_sm9  [NB*9 *HWX];    // softmax scratch (k=3 masks)
__device__ float g_mlh  [NB*25*HWX];    // mask_lr_hr -> mask_lr (in-place add)
__device__ float g_sm25 [NB*25*HWX];    // softmax(mask_lr_hr)
__device__ float g_mlll [NB*25*HW2];    // enc(clf)
__device__ float g_e2clf[NB*9 *HW2];    // enc2(clf)

// ---------------------------------------------------------------------------
// conv1x1 as SGEMM: Y[n][oc][p] = b[oc] + sum_c W[oc][c] * X[n][c][p]
// M=64, K=256; BN=256 pixels, BK=16; thread tile 8x8 (8 oc x 8 pixels)
// ---------------------------------------------------------------------------
__global__ void __launch_bounds__(256) conv1x1_kernel(
    const float* __restrict__ X, const float* __restrict__ Wt,
    const float* __restrict__ Bi, float* __restrict__ Y, int P)
{
    __shared__ float Ws[16][64];
    __shared__ float Xs[16][256];
    const int n  = blockIdx.z;
    const int p0 = blockIdx.x * 256;
    const int tid = threadIdx.x;
    const int tx = tid & 31;   // pixel group (8 px each)
    const int ty = tid >> 5;   // oc group (8 oc each)
    const float* Xn = X + (size_t)n * CIN * P;

    float acc[8][8];
#pragma unroll
    for (int i = 0; i < 8; i++)
#pragma unroll
        for (int j = 0; j < 8; j++) acc[i][j] = 0.f;

    for (int k0 = 0; k0 < CIN; k0 += 16) {
        // load 16x64 weight tile
#pragma unroll
        for (int i = 0; i < 4; i++) {
            int idx = i * 256 + tid;
            int kk = idx >> 6, mm = idx & 63;
            Ws[kk][mm] = Wt[mm * CIN + k0 + kk];
        }
        // load 16x256 activation tile (float4, coalesced)
#pragma unroll
        for (int i = 0; i < 4; i++) {
            int idx = i * 256 + tid;
            int kk = idx >> 6;
            int pp = (idx & 63) << 2;
            *(float4*)&Xs[kk][pp] =
                *(const float4*)&Xn[(size_t)(k0 + kk) * P + p0 + pp];
        }
        __syncthreads();
#pragma unroll
        for (int k = 0; k < 16; k++) {
            float rw[8], rx[8];
            *(float4*)&rw[0] = *(float4*)&Ws[k][ty * 8];
            *(float4*)&rw[4] = *(float4*)&Ws[k][ty * 8 + 4];
            *(float4*)&rx[0] = *(float4*)&Xs[k][tx * 8];
            *(float4*)&rx[4] = *(float4*)&Xs[k][tx * 8 + 4];
#pragma unroll
            for (int i = 0; i < 8; i++)
#pragma unroll
                for (int j = 0; j < 8; j++)
                    acc[i][j] += rw[i] * rx[j];
        }
        __syncthreads();
    }

#pragma unroll
    for (int i = 0; i < 8; i++) {
        int oc = ty * 8 + i;
        float bv = Bi[oc];
        size_t base = ((size_t)n * CCC + oc) * P + p0 + tx * 8;
        float4 v0 = make_float4(acc[i][0]+bv, acc[i][1]+bv, acc[i][2]+bv, acc[i][3]+bv);
        float4 v1 = make_float4(acc[i][4]+bv, acc[i][5]+bv, acc[i][6]+bv, acc[i][7]+bv);
        *(float4*)&Y[base]     = v0;
        *(float4*)&Y[base + 4] = v1;
    }
}

// ---------------------------------------------------------------------------
// conv3x3, pad=1, Cin=64, Cout=K2 (9 or 25).
// blockDim(32,4); each thread produces XPT consecutive x-pixels in one row.
// tile = full row width (32*XPT == Wi) x 4 rows, +1 halo each side.
// ---------------------------------------------------------------------------
template<int K2, int XPT>
__global__ void __launch_bounds__(128) conv3x3_kernel(
    const float* __restrict__ X, const float* __restrict__ Wt,
    const float* __restrict__ Bi, float* __restrict__ Y,
    int Hi, int Wi)
{
    const int TW = 32 * XPT;          // == Wi
    const int n  = blockIdx.z;
    const int y0 = blockIdx.y * 4;
    const int tx = threadIdx.x, ty = threadIdx.y;
    const int tid = ty * 32 + tx;

    __shared__ float ws[K2 * 9];
    __shared__ float tile[6][32 * XPT + 8];

    float acc[K2][XPT];
#pragma unroll
    for (int o = 0; o < K2; o++)
#pragma unroll
        for (int j = 0; j < XPT; j++) acc[o][j] = 0.f;

    const int HWi = Hi * Wi;
    const float* Xn = X + (size_t)n * CCC * HWi;

    for (int c = 0; c < CCC; c++) {
        __syncthreads();
        // per-channel weights: K2*9 floats into smem
        for (int i = tid; i < K2 * 9; i += 128)
            ws[i] = Wt[((i / 9) * CCC + c) * 9 + (i % 9)];
        // input tile with halo
        const float* Xc = Xn + (size_t)c * HWi;
        for (int i = tid; i < 6 * (TW + 2); i += 128) {
            int r = i / (TW + 2), cc2 = i % (TW + 2);
            int gy = y0 - 1 + r, gx = cc2 - 1;
            float v = 0.f;
            if ((unsigned)gy < (unsigned)Hi && (unsigned)gx < (unsigned)Wi)
                v = Xc[gy * Wi + gx];
            tile[r][cc2] = v;
        }
        __syncthreads();

        float win[3][XPT + 2];
#pragma unroll
        for (int r = 0; r < 3; r++)
#pragma unroll
            for (int j = 0; j < XPT + 2; j++)
                win[r][j] = tile[ty + r][tx * XPT + j];

#pragma unroll
        for (int o = 0; o < K2; o++)
#pragma unroll
            for (int r = 0; r < 3; r++)
#pragma unroll
                for (int dc = 0; dc < 3; dc++) {
                    float w = ws[o * 9 + r * 3 + dc];
#pragma unroll
                    for (int j = 0; j < XPT; j++)
                        acc[o][j] += w * win[r][j + dc];
                }
    }

    const int y = y0 + ty;
#pragma unroll
    for (int o = 0; o < K2; o++) {
        float bv = Bi[o];
        size_t base = (((size_t)n * K2 + o) * Hi + y) * Wi + tx * XPT;
#pragma unroll
        for (int j = 0; j < XPT; j++) Y[base + j] = acc[o][j] + bv;
    }
}

// ---------------------------------------------------------------------------
// kernel_normalizer == per-pixel softmax over K2 channel axis (mc==1).
// Layout [n][K2][HWX]. One thread per pixel; coalesced strided reads.
// ---------------------------------------------------------------------------
template<int K2>
__global__ void softmax_kernel(const float* __restrict__ X, float* __restrict__ Y)
{
    const int p = blockIdx.x * 256 + threadIdx.x;
    const int n = blockIdx.z;
    const float* xp = X + (size_t)n * K2 * HWX + p;
    float v[K2];
    float mx = -1e30f;
#pragma unroll
    for (int j = 0; j < K2; j++) { v[j] = xp[(size_t)j * HWX]; mx = fmaxf(mx, v[j]); }
    float s = 0.f;
#pragma unroll
    for (int j = 0; j < K2; j++) { v[j] = __expf(v[j] - mx); s += v[j]; }
    float inv = 1.f / s;
    float* yp = Y + (size_t)n * K2 * HWX + p;
#pragma unroll
    for (int j = 0; j < K2; j++) yp[(size_t)j * HWX] = v[j] * inv;
}

// ---------------------------------------------------------------------------
// CARAFE scale=1, k=3, fused residual: Y = 2*F - sum_j m[j]*window[j]
// blockDim(32,4); thread handles 4 consecutive x-pixels in one row.
// ---------------------------------------------------------------------------
__global__ void __launch_bounds__(128) carafe_s1_kernel(
    const float* __restrict__ F, const float* __restrict__ M,
    float* __restrict__ Y, int C)
{
    const int n  = blockIdx.z;
    const int y0 = blockIdx.y * 4;
    const int tx = threadIdx.x, ty = threadIdx.y;
    const int tid = ty * 32 + tx;
    __shared__ float tile[6][136];

    const int y  = y0 + ty;
    const int xb = tx * 4;

    // normalized masks for this thread's 4 pixels (loaded once)
    float mk[9][4];
    const float* Mn = M + (size_t)n * 9 * HWX;
#pragma unroll
    for (int j = 0; j < 9; j++) {
        float4 m4 = *(const float4*)&Mn[(size_t)j * HWX + y * WW + xb];
        mk[j][0] = m4.x; mk[j][1] = m4.y; mk[j][2] = m4.z; mk[j][3] = m4.w;
    }

    const float* Fn = F + (size_t)n * C * HWX;
    float* Yn = Y + (size_t)n * C * HWX;

    for (int c = 0; c < C; c++) {
        __syncthreads();
        const float* Fc = Fn + (size_t)c * HWX;
        for (int i = tid; i < 6 * 130; i += 128) {
            int r = i / 130, cc2 = i % 130;
            int gy = y0 - 1 + r, gx = cc2 - 1;
            float v = 0.f;
            if ((unsigned)gy < HH && (unsigned)gx < WW) v = Fc[gy * WW + gx];
            tile[r][cc2] = v;
        }
        __syncthreads();

        float win[3][6];
#pragma unroll
        for (int r = 0; r < 3; r++)
#pragma unroll
            for (int j = 0; j < 6; j++)
                win[r][j] = tile[ty + r][xb + j];

        float out[4];
#pragma unroll
        for (int px = 0; px < 4; px++) out[px] = 2.f * win[1][px + 1];
#pragma unroll
        for (int r = 0; r < 3; r++)
#pragma unroll
            for (int dc = 0; dc < 3; dc++)
#pragma unroll
                for (int px = 0; px < 4; px++)
                    out[px] -= mk[r * 3 + dc][px] * win[r][px + dc];

        *(float4*)&Yn[(size_t)c * HWX + y * WW + xb] =
            make_float4(out[0], out[1], out[2], out[3]);
    }
}

// ---------------------------------------------------------------------------
// CARAFE scale=2, k=5 (nearest-upsampled feature taps).
// F: [n][C][64][64], M: [n][25][128][128] normalized, Y: [n][C][128][128].
// Thread handles 2 output x-pixels that share one 5x5 low-res window.
// Optional fused add of a base tensor (in-place safe: reads only own element).
// ---------------------------------------------------------------------------
template<bool ADD>
__global__ void __launch_bounds__(256) carafe_s2_kernel(
    const float* __restrict__ F, const float* __restrict__ M,
    const float* __restrict__ B, float* __restrict__ Y, int C)
{
    const int n  = blockIdx.z;
    const int x0 = blockIdx.x * 64, y0 = blockIdx.y * 8;
    const int tx = threadIdx.x, ty = threadIdx.y;
    const int tid = ty * 32 + tx;
    const int xo = x0 + tx * 2;
    const int yo = y0 + ty;

    __shared__ float tile[8][36];

    float mk0[25], mk1[25];
    const float* Mn = M + (size_t)n * 25 * HWX;
#pragma unroll
    for (int j = 0; j < 25; j++) {
        float2 m2 = *(const float2*)&Mn[(size_t)j * HWX + yo * WW + xo];
        mk0[j] = m2.x; mk1[j] = m2.y;
    }

    const int ylb = y0 / 2 - 2, xlb = x0 / 2 - 2;
    const int rb  = ty >> 1;
    const float* Fn = F + (size_t)n * C * HW2;

    for (int c = 0; c < C; c++) {
        __syncthreads();
        const float* Fc = Fn + (size_t)c * HW2;
        for (int i = tid; i < 8 * 36; i += 256) {
            int r = i / 36, cc2 = i % 36;
            int gy = ylb + r, gx = xlb + cc2;
            float v = 0.f;
            if ((unsigned)gy < H2 && (unsigned)gx < W2) v = Fc[gy * W2 + gx];
            tile[r][cc2] = v;
        }
        __syncthreads();

        float a0 = 0.f, a1 = 0.f;
#pragma unroll
        for (int ki = 0; ki < 5; ki++)
#pragma unroll
            for (int kj = 0; kj < 5; kj++) {
                float v = tile[rb + ki][tx + kj];
                a0 += v * mk0[ki * 5 + kj];
                a1 += v * mk1[ki * 5 + kj];
            }

        size_t oidx = (((size_t)n * C + c) * HH + yo) * WW + xo;
        if (ADD) {
            float2 b2 = *(const float2*)&B[oidx];
            a0 += b2.x; a1 += b2.y;
        }
        *(float2*)&Y[oidx] = make_float2(a0, a1);
    }
}

// ---------------------------------------------------------------------------
// Orchestration (graph-capturable: kernel launches only)
// ---------------------------------------------------------------------------
extern "C" void kernel_launch(void* const* d_in, const int* in_sizes, int n_in,
                              void* d_out, int out_size)
{
    const float* hr_feat = (const float*)d_in[0];
    const float* lr_feat = (const float*)d_in[1];
    const float* hr_w    = (const float*)d_in[2];
    const float* hr_b    = (const float*)d_in[3];
    const float* lr_w    = (const float*)d_in[4];
    const float* lr_b    = (const float*)d_in[5];
    const float* enc_w   = (const float*)d_in[6];
    const float* enc_b   = (const float*)d_in[7];
    const float* enc2_w  = (const float*)d_in[8];
    const float* enc2_b  = (const float*)d_in[9];
    float* out = (float*)d_out;

    float *p_chf, *p_chf2, *p_clf, *p_mhh, *p_sm9, *p_mlh, *p_sm25, *p_mlll, *p_e2clf;
    cudaGetSymbolAddress((void**)&p_chf,   g_chf);
    cudaGetSymbolAddress((void**)&p_chf2,  g_chf2);
    cudaGetSymbolAddress((void**)&p_clf,   g_clf);
    cudaGetSymbolAddress((void**)&p_mhh,   g_mhh);
    cudaGetSymbolAddress((void**)&p_sm9,   g_sm9);
    cudaGetSymbolAddress((void**)&p_mlh,   g_mlh);
    cudaGetSymbolAddress((void**)&p_sm25,  g_sm25);
    cudaGetSymbolAddress((void**)&p_mlll,  g_mlll);
    cudaGetSymbolAddress((void**)&p_e2clf, g_e2clf);

    const size_t MASK_SZ = (size_t)NB * 25 * HWX;   // 1,638,400
    const size_t FEAT_SZ = (size_t)NB * 256 * HWX;  // 16,777,216
    float* out_mask = out;                          // mask_lr_out
    float* out_hr   = out + MASK_SZ;                // hr_out
    float* out_lr   = out + MASK_SZ + FEAT_SZ;      // lr_out

    dim3 bm(32, 4), bm2(32, 8);

    // chf = conv1x1(hr_feat), clf = conv1x1(lr_feat)
    conv1x1_kernel<<<dim3(HWX/256, 1, NB), 256>>>(hr_feat, hr_w, hr_b, p_chf, HWX);
    conv1x1_kernel<<<dim3(HW2/256, 1, NB), 256>>>(lr_feat, lr_w, lr_b, p_clf, HW2);

    // mask_hr_hr = enc2(chf); mask_hr_init = softmax9
    conv3x3_kernel<9, 4><<<dim3(1, HH/4, NB), bm>>>(p_chf, enc2_w, enc2_b, p_mhh, HH, WW);
    softmax_kernel<9><<<dim3(HWX/256, 1, NB), 256>>>(p_mhh, p_sm9);

    // chf = 2*chf - carafe(chf, mask_hr_init, 3, 1)
    carafe_s1_kernel<<<dim3(1, HH/4, NB), bm>>>(p_chf, p_sm9, p_chf2, CCC);

    // mask_lr_hr = enc(chf'); mask_lr_lr_lr = enc(clf)
    conv3x3_kernel<25, 4><<<dim3(1, HH/4, NB), bm>>>(p_chf2, enc_w, enc_b, p_mlh, HH, WW);
    conv3x3_kernel<25, 2><<<dim3(1, H2/4, NB), bm>>>(p_clf, enc_w, enc_b, p_mlll, H2, W2);

    // mask_lr = mask_lr_hr + carafe(mask_lr_lr_lr, softmax25(mask_lr_hr), 5, 2)
    softmax_kernel<25><<<dim3(HWX/256, 1, NB), 256>>>(p_mlh, p_sm25);
    carafe_s2_kernel<true><<<dim3(WW/64, HH/8, NB), bm2>>>(p_mlll, p_sm25, p_mlh, p_mlh, 25);

    // mask_lr_out = softmax25(mask_lr)  -> output 0 (also reused as operand)
    softmax_kernel<25><<<dim3(HWX/256, 1, NB), 256>>>(p_mlh, out_mask);

    // mask_hr = mask_hr_hr + carafe(enc2(clf), mask_lr_out, 5, 2)
    conv3x3_kernel<9, 2><<<dim3(1, H2/4, NB), bm>>>(p_clf, enc2_w, enc2_b, p_e2clf, H2, W2);
    carafe_s2_kernel<true><<<dim3(WW/64, HH/8, NB), bm2>>>(p_e2clf, out_mask, p_mhh, p_mhh, 9);

    // hr_out = 2*hr_feat - carafe(hr_feat, softmax9(mask_hr), 3, 1)  -> output 1
    softmax_kernel<9><<<dim3(HWX/256, 1, NB), 256>>>(p_mhh, p_sm9);
    carafe_s1_kernel<<<dim3(1, HH/4, NB), bm>>>(hr_feat, p_sm9, out_hr, 256);

    // lr_out = carafe(lr_feat, mask_lr_out, 5, 2)  -> output 2
    carafe_s2_kernel<false><<<dim3(WW/64, HH/8, NB), bm2>>>(lr_feat, out_mask, nullptr, out_lr, 256);
}